// round 9
// baseline (speedup 1.0000x reference)
#include <cuda_runtime.h>
#include <cuda_bf16.h>

// MaskedPooling: out[b,d] = sum_t x[b,t,d]*keep[b,t] / sum_t keep[b,t]
// x: [32,4096,512] f32, mask: [32,4096] int32 (nonzero = excluded).
// R9: 2048 small CTAs (64 rows each) for ~75% occupancy; batch-4 branch-free
// mainloop (regs ~40 so 12 CTAs/SM fit); predicated-weight tail batch (no
// serial dependent tail); __ldcs streaming loads; fused last-CTA reduction.

#define B_DIM 32
#define T_DIM 4096
#define D_DIM 512
#define S_SPLIT 64
#define ROWS (T_DIM / S_SPLIT)   // 64
#define TPB 128                  // 128 threads * float4 = 512 floats = D
#define DSTRIDE (D_DIM / 4)      // 128 float4 per row

__device__ float g_partial[B_DIM * S_SPLIT * D_DIM];  // 4 MB scratch
__device__ float g_count[B_DIM * S_SPLIT];
__device__ int   g_sem[B_DIM];                        // zero-init; self-resetting

__global__ __launch_bounds__(TPB) void mp_fused_kernel(
    const float* __restrict__ x, const int* __restrict__ mask,
    float* __restrict__ out) {
    const int s = blockIdx.x;   // T-chunk
    const int b = blockIdx.y;   // batch
    const int tid = threadIdx.x;
    const int lane = tid & 31;
    const int wid = tid >> 5;
    const int t0 = s * ROWS;

    __shared__ int m[ROWS];
    __shared__ short idxbuf[ROWS];
    __shared__ int wcnt[5];
    __shared__ bool isLast;

    // stage mask chunk (64 int32 = 256 B)
    if (tid < ROWS / 4) {
        reinterpret_cast<int4*>(m)[tid] =
            reinterpret_cast<const int4*>(mask + b * T_DIM + t0)[tid];
    }
    __syncthreads();

    // compact kept-row indices (rows live in warps 0-1; warps 2-3 contribute 0)
    bool kflag = (tid < ROWS) && (m[tid < ROWS ? tid : 0] == 0);
    unsigned bal = __ballot_sync(0xffffffffu, kflag);
    if (lane == 0) wcnt[wid] = __popc(bal);
    __syncthreads();
    if (tid == 0) {
        int sum = 0;
        #pragma unroll
        for (int j = 0; j < 4; j++) { int c = wcnt[j]; wcnt[j] = sum; sum += c; }
        wcnt[4] = sum;
    }
    __syncthreads();
    const int nkeep = wcnt[4];
    if (kflag) {
        int pos = wcnt[wid] + __popc(bal & ((1u << lane) - 1u));
        idxbuf[pos] = (short)tid;
    }
    __syncthreads();

    // branch-free mainloop: batch of 4 independent LDG.128, 2 accumulators
    const float4* xp = reinterpret_cast<const float4*>(
        x + ((size_t)b * T_DIM + t0) * D_DIM);

    float4 acc0 = make_float4(0.f, 0.f, 0.f, 0.f);
    float4 acc1 = make_float4(0.f, 0.f, 0.f, 0.f);
    int i = 0;
    for (; i + 4 <= nkeep; i += 4) {
        float4 v0 = __ldcs(&xp[(size_t)idxbuf[i + 0] * DSTRIDE + tid]);
        float4 v1 = __ldcs(&xp[(size_t)idxbuf[i + 1] * DSTRIDE + tid]);
        float4 v2 = __ldcs(&xp[(size_t)idxbuf[i + 2] * DSTRIDE + tid]);
        float4 v3 = __ldcs(&xp[(size_t)idxbuf[i + 3] * DSTRIDE + tid]);
        acc0.x += v0.x; acc0.y += v0.y; acc0.z += v0.z; acc0.w += v0.w;
        acc1.x += v1.x; acc1.y += v1.y; acc1.z += v1.z; acc1.w += v1.w;
        acc0.x += v2.x; acc0.y += v2.y; acc0.z += v2.z; acc0.w += v2.w;
        acc1.x += v3.x; acc1.y += v3.y; acc1.z += v3.z; acc1.w += v3.w;
    }
    // predicated tail batch: clamped indices, zero weights (no dependent chain)
    if (i < nkeep) {
        #pragma unroll
        for (int j = 0; j < 4; j++) {
            int k = i + j;
            bool ok = (k < nkeep);
            int r = idxbuf[ok ? k : i];
            float w = ok ? 1.f : 0.f;
            float4 v = __ldcs(&xp[(size_t)r * DSTRIDE + tid]);
            acc0.x = fmaf(w, v.x, acc0.x);
            acc0.y = fmaf(w, v.y, acc0.y);
            acc0.z = fmaf(w, v.z, acc0.z);
            acc0.w = fmaf(w, v.w, acc0.w);
        }
    }
    acc0.x += acc1.x; acc0.y += acc1.y; acc0.z += acc1.z; acc0.w += acc1.w;

    reinterpret_cast<float4*>(g_partial)[(size_t)(b * S_SPLIT + s) * DSTRIDE + tid] = acc0;
    if (tid == 0) g_count[b * S_SPLIT + s] = (float)nkeep;

    // ALL warps must finish partial stores before this CTA arrives.
    __syncthreads();
    __threadfence();
    if (tid == 0) {
        int v = atomicAdd(&g_sem[b], 1);
        isLast = (v == S_SPLIT - 1);
    }
    __syncthreads();

    if (isLast) {
        float denom = 0.f;
        #pragma unroll 8
        for (int ss = 0; ss < S_SPLIT; ss++) denom += g_count[b * S_SPLIT + ss];

        float4 r0 = make_float4(0.f, 0.f, 0.f, 0.f);
        float4 r1 = make_float4(0.f, 0.f, 0.f, 0.f);
        const float4* gp = reinterpret_cast<const float4*>(g_partial);
        #pragma unroll 8
        for (int ss = 0; ss < S_SPLIT; ss += 2) {
            float4 v0 = gp[(size_t)(b * S_SPLIT + ss) * DSTRIDE + tid];
            float4 v1 = gp[(size_t)(b * S_SPLIT + ss + 1) * DSTRIDE + tid];
            r0.x += v0.x; r0.y += v0.y; r0.z += v0.z; r0.w += v0.w;
            r1.x += v1.x; r1.y += v1.y; r1.z += v1.z; r1.w += v1.w;
        }
        r0.x += r1.x; r0.y += r1.y; r0.z += r1.z; r0.w += r1.w;
        float inv = 1.f / denom;
        r0.x *= inv; r0.y *= inv; r0.z *= inv; r0.w *= inv;
        reinterpret_cast<float4*>(out)[(size_t)b * DSTRIDE + tid] = r0;

        if (tid == 0) g_sem[b] = 0;  // reset for next graph replay
    }
}

extern "C" void kernel_launch(void* const* d_in, const int* in_sizes, int n_in,
                              void* d_out, int out_size) {
    const float* x = (const float*)d_in[0];
    const int* mask = (const int*)d_in[1];
    float* out = (float*)d_out;

    dim3 grid(S_SPLIT, B_DIM);
    mp_fused_kernel<<<grid, TPB>>>(x, mask, out);
}

// round 10
// speedup vs baseline: 1.2228x; 1.2228x over previous
#include <cuda_runtime.h>
#include <cuda_bf16.h>

// MaskedPooling: out[b,d] = sum_t x[b,t,d]*keep[b,t] / sum_t keep[b,t]
// x: [32,4096,512] f32, mask: [32,4096] int32 (nonzero = excluded).
// R10: back to 1024 CTAs (128 rows each, R8's best grid) + software-pipelined
// double-buffered batch-4 mainloop so loads are continuously in flight
// (R4/R8/R9 showed DRAM pinned ~50-55% regardless of occupancy -> duty-cycle
// bubble between load batches was the limiter, not concurrency).

#define B_DIM 32
#define T_DIM 4096
#define D_DIM 512
#define S_SPLIT 32
#define ROWS (T_DIM / S_SPLIT)   // 128
#define TPB 128                  // 128 threads * float4 = 512 floats = D
#define DSTRIDE (D_DIM / 4)      // 128 float4 per row

__device__ float g_partial[B_DIM * S_SPLIT * D_DIM];  // 2 MB scratch
__device__ float g_count[B_DIM * S_SPLIT];
__device__ int   g_sem[B_DIM];                        // zero-init; self-resetting

__global__ __launch_bounds__(TPB, 8) void mp_fused_kernel(
    const float* __restrict__ x, const int* __restrict__ mask,
    float* __restrict__ out) {
    const int s = blockIdx.x;   // T-chunk
    const int b = blockIdx.y;   // batch
    const int tid = threadIdx.x;
    const int lane = tid & 31;
    const int wid = tid >> 5;
    const int t0 = s * ROWS;

    __shared__ int m[ROWS];
    __shared__ short idxbuf[ROWS];
    __shared__ int wcnt[5];
    __shared__ bool isLast;

    // stage mask chunk (128 int32 = 512 B)
    if (tid < ROWS / 4) {
        reinterpret_cast<int4*>(m)[tid] =
            reinterpret_cast<const int4*>(mask + b * T_DIM + t0)[tid];
    }
    __syncthreads();

    // compact kept-row indices: single ballot round (ROWS == TPB)
    bool kflag = (m[tid] == 0);
    unsigned bal = __ballot_sync(0xffffffffu, kflag);
    if (lane == 0) wcnt[wid] = __popc(bal);
    __syncthreads();
    if (tid == 0) {
        int sum = 0;
        #pragma unroll
        for (int j = 0; j < 4; j++) { int c = wcnt[j]; wcnt[j] = sum; sum += c; }
        wcnt[4] = sum;
    }
    __syncthreads();
    const int nkeep = wcnt[4];
    if (kflag) {
        int pos = wcnt[wid] + __popc(bal & ((1u << lane) - 1u));
        idxbuf[pos] = (short)tid;
    }
    __syncthreads();

    const float4* xp = reinterpret_cast<const float4*>(
        x + ((size_t)b * T_DIM + t0) * D_DIM);

    float4 acc0 = make_float4(0.f, 0.f, 0.f, 0.f);
    float4 acc1 = make_float4(0.f, 0.f, 0.f, 0.f);

    // software-pipelined mainloop: double-buffered batch of 4 LDG.128.
    // issue loads for batch j+1, THEN accumulate batch j -> loads always in flight.
    int i = 0;
    if (nkeep >= 8) {
        float4 b0 = __ldcs(&xp[(size_t)idxbuf[0] * DSTRIDE + tid]);
        float4 b1 = __ldcs(&xp[(size_t)idxbuf[1] * DSTRIDE + tid]);
        float4 b2 = __ldcs(&xp[(size_t)idxbuf[2] * DSTRIDE + tid]);
        float4 b3 = __ldcs(&xp[(size_t)idxbuf[3] * DSTRIDE + tid]);
        for (i = 4; i + 4 <= nkeep; i += 4) {
            float4 n0 = __ldcs(&xp[(size_t)idxbuf[i + 0] * DSTRIDE + tid]);
            float4 n1 = __ldcs(&xp[(size_t)idxbuf[i + 1] * DSTRIDE + tid]);
            float4 n2 = __ldcs(&xp[(size_t)idxbuf[i + 2] * DSTRIDE + tid]);
            float4 n3 = __ldcs(&xp[(size_t)idxbuf[i + 3] * DSTRIDE + tid]);
            acc0.x += b0.x; acc0.y += b0.y; acc0.z += b0.z; acc0.w += b0.w;
            acc1.x += b1.x; acc1.y += b1.y; acc1.z += b1.z; acc1.w += b1.w;
            acc0.x += b2.x; acc0.y += b2.y; acc0.z += b2.z; acc0.w += b2.w;
            acc1.x += b3.x; acc1.y += b3.y; acc1.z += b3.z; acc1.w += b3.w;
            b0 = n0; b1 = n1; b2 = n2; b3 = n3;
        }
        acc0.x += b0.x; acc0.y += b0.y; acc0.z += b0.z; acc0.w += b0.w;
        acc1.x += b1.x; acc1.y += b1.y; acc1.z += b1.z; acc1.w += b1.w;
        acc0.x += b2.x; acc0.y += b2.y; acc0.z += b2.z; acc0.w += b2.w;
        acc1.x += b3.x; acc1.y += b3.y; acc1.z += b3.z; acc1.w += b3.w;
    }
    // predicated tail batches: clamped indices, zero weights (no serial chain)
    while (i < nkeep) {
        #pragma unroll
        for (int j = 0; j < 4; j++) {
            int k = i + j;
            bool ok = (k < nkeep);
            int r = idxbuf[ok ? k : i];
            float w = ok ? 1.f : 0.f;
            float4 v = __ldcs(&xp[(size_t)r * DSTRIDE + tid]);
            acc0.x = fmaf(w, v.x, acc0.x);
            acc0.y = fmaf(w, v.y, acc0.y);
            acc0.z = fmaf(w, v.z, acc0.z);
            acc0.w = fmaf(w, v.w, acc0.w);
        }
        i += 4;
    }
    acc0.x += acc1.x; acc0.y += acc1.y; acc0.z += acc1.z; acc0.w += acc1.w;

    reinterpret_cast<float4*>(g_partial)[(size_t)(b * S_SPLIT + s) * DSTRIDE + tid] = acc0;
    if (tid == 0) g_count[b * S_SPLIT + s] = (float)nkeep;

    // ALL warps must finish partial stores before this CTA arrives.
    __syncthreads();
    __threadfence();
    if (tid == 0) {
        int v = atomicAdd(&g_sem[b], 1);
        isLast = (v == S_SPLIT - 1);
    }
    __syncthreads();

    if (isLast) {
        float denom = 0.f;
        #pragma unroll 8
        for (int ss = 0; ss < S_SPLIT; ss++) denom += g_count[b * S_SPLIT + ss];

        float4 r0 = make_float4(0.f, 0.f, 0.f, 0.f);
        float4 r1 = make_float4(0.f, 0.f, 0.f, 0.f);
        const float4* gp = reinterpret_cast<const float4*>(g_partial);
        #pragma unroll 8
        for (int ss = 0; ss < S_SPLIT; ss += 2) {
            float4 v0 = gp[(size_t)(b * S_SPLIT + ss) * DSTRIDE + tid];
            float4 v1 = gp[(size_t)(b * S_SPLIT + ss + 1) * DSTRIDE + tid];
            r0.x += v0.x; r0.y += v0.y; r0.z += v0.z; r0.w += v0.w;
            r1.x += v1.x; r1.y += v1.y; r1.z += v1.z; r1.w += v1.w;
        }
        r0.x += r1.x; r0.y += r1.y; r0.z += r1.z; r0.w += r1.w;
        float inv = 1.f / denom;
        r0.x *= inv; r0.y *= inv; r0.z *= inv; r0.w *= inv;
        reinterpret_cast<float4*>(out)[(size_t)b * DSTRIDE + tid] = r0;

        if (tid == 0) g_sem[b] = 0;  // reset for next graph replay
    }
}

extern "C" void kernel_launch(void* const* d_in, const int* in_sizes, int n_in,
                              void* d_out, int out_size) {
    const float* x = (const float*)d_in[0];
    const int* mask = (const int*)d_in[1];
    float* out = (float*)d_out;

    dim3 grid(S_SPLIT, B_DIM);
    mp_fused_kernel<<<grid, TPB>>>(x, mask, out);
}

// round 11
// speedup vs baseline: 1.2242x; 1.0011x over previous
#include <cuda_runtime.h>
#include <cuda_bf16.h>

// MaskedPooling: out[b,d] = sum_t x[b,t,d]*keep[b,t] / sum_t keep[b,t]
// x: [32,4096,512] f32, mask: [32,4096] int32 (nonzero = excluded).
// R11: distance-2 software pipeline (3 buffer sets of 4 LDG.128 -> ~8-12 loads
// continuously in flight per thread; R10's depth-1 pipeline got DRAM 55->61%,
// drain point between batches remained). Precomputed byte offsets in smem cut
// addressing work between LDGs. 1024 CTAs, fused last-CTA reduction.

#define B_DIM 32
#define T_DIM 4096
#define D_DIM 512
#define S_SPLIT 32
#define ROWS (T_DIM / S_SPLIT)   // 128
#define TPB 128                  // 128 threads * float4 = 512 floats = D
#define DSTRIDE (D_DIM / 4)      // 128 float4 per row
#define ROW_BYTES (D_DIM * 4)    // 2048

__device__ float g_partial[B_DIM * S_SPLIT * D_DIM];  // 2 MB scratch
__device__ float g_count[B_DIM * S_SPLIT];
__device__ int   g_sem[B_DIM];                        // zero-init; self-resetting

#define ACC4(A, V) do { (A).x += (V).x; (A).y += (V).y; (A).z += (V).z; (A).w += (V).w; } while (0)

__global__ __launch_bounds__(TPB, 7) void mp_fused_kernel(
    const float* __restrict__ x, const int* __restrict__ mask,
    float* __restrict__ out) {
    const int s = blockIdx.x;   // T-chunk
    const int b = blockIdx.y;   // batch
    const int tid = threadIdx.x;
    const int lane = tid & 31;
    const int wid = tid >> 5;
    const int t0 = s * ROWS;

    __shared__ int m[ROWS];
    __shared__ int offbuf[ROWS];     // precomputed byte offsets of kept rows
    __shared__ int wcnt[5];
    __shared__ bool isLast;

    // stage mask chunk (128 int32 = 512 B)
    if (tid < ROWS / 4) {
        reinterpret_cast<int4*>(m)[tid] =
            reinterpret_cast<const int4*>(mask + b * T_DIM + t0)[tid];
    }
    __syncthreads();

    // compact kept-row BYTE OFFSETS: single ballot round (ROWS == TPB)
    bool kflag = (m[tid] == 0);
    unsigned bal = __ballot_sync(0xffffffffu, kflag);
    if (lane == 0) wcnt[wid] = __popc(bal);
    __syncthreads();
    if (tid == 0) {
        int sum = 0;
        #pragma unroll
        for (int j = 0; j < 4; j++) { int c = wcnt[j]; wcnt[j] = sum; sum += c; }
        wcnt[4] = sum;
    }
    __syncthreads();
    const int nkeep = wcnt[4];
    if (kflag) {
        int pos = wcnt[wid] + __popc(bal & ((1u << lane) - 1u));
        offbuf[pos] = tid * ROW_BYTES;
    }
    __syncthreads();

    const char* xbase = reinterpret_cast<const char*>(
        x + ((size_t)b * T_DIM + t0) * D_DIM) + tid * 16;

    float4 acc0 = make_float4(0.f, 0.f, 0.f, 0.f);
    float4 acc1 = make_float4(0.f, 0.f, 0.f, 0.f);

    #define LD4(dst, base_i) do { \
        (dst)[0] = __ldcs(reinterpret_cast<const float4*>(xbase + offbuf[(base_i) + 0])); \
        (dst)[1] = __ldcs(reinterpret_cast<const float4*>(xbase + offbuf[(base_i) + 1])); \
        (dst)[2] = __ldcs(reinterpret_cast<const float4*>(xbase + offbuf[(base_i) + 2])); \
        (dst)[3] = __ldcs(reinterpret_cast<const float4*>(xbase + offbuf[(base_i) + 3])); \
    } while (0)

    int i = 0;
    if (nkeep >= 12) {
        // distance-2 pipeline: buffers A (oldest), B, and incoming N
        float4 A[4], Bf[4];
        LD4(A, 0);
        LD4(Bf, 4);
        for (i = 8; i + 4 <= nkeep; i += 4) {
            float4 N[4];
            LD4(N, i);
            ACC4(acc0, A[0]); ACC4(acc1, A[1]); ACC4(acc0, A[2]); ACC4(acc1, A[3]);
            A[0] = Bf[0]; A[1] = Bf[1]; A[2] = Bf[2]; A[3] = Bf[3];
            Bf[0] = N[0]; Bf[1] = N[1]; Bf[2] = N[2]; Bf[3] = N[3];
        }
        ACC4(acc0, A[0]); ACC4(acc1, A[1]); ACC4(acc0, A[2]); ACC4(acc1, A[3]);
        ACC4(acc0, Bf[0]); ACC4(acc1, Bf[1]); ACC4(acc0, Bf[2]); ACC4(acc1, Bf[3]);
    }
    // predicated tail batches: clamped offsets, zero weights (no serial chain)
    while (i < nkeep) {
        #pragma unroll
        for (int j = 0; j < 4; j++) {
            int k = i + j;
            bool ok = (k < nkeep);
            int off = offbuf[ok ? k : i];
            float w = ok ? 1.f : 0.f;
            float4 v = __ldcs(reinterpret_cast<const float4*>(xbase + off));
            acc0.x = fmaf(w, v.x, acc0.x);
            acc0.y = fmaf(w, v.y, acc0.y);
            acc0.z = fmaf(w, v.z, acc0.z);
            acc0.w = fmaf(w, v.w, acc0.w);
        }
        i += 4;
    }
    ACC4(acc0, acc1);

    reinterpret_cast<float4*>(g_partial)[(size_t)(b * S_SPLIT + s) * DSTRIDE + tid] = acc0;
    if (tid == 0) g_count[b * S_SPLIT + s] = (float)nkeep;

    // ALL warps must finish partial stores before this CTA arrives.
    __syncthreads();
    __threadfence();
    if (tid == 0) {
        int v = atomicAdd(&g_sem[b], 1);
        isLast = (v == S_SPLIT - 1);
    }
    __syncthreads();

    if (isLast) {
        float denom = 0.f;
        #pragma unroll 8
        for (int ss = 0; ss < S_SPLIT; ss++) denom += g_count[b * S_SPLIT + ss];

        float4 r0 = make_float4(0.f, 0.f, 0.f, 0.f);
        float4 r1 = make_float4(0.f, 0.f, 0.f, 0.f);
        const float4* gp = reinterpret_cast<const float4*>(g_partial);
        #pragma unroll 8
        for (int ss = 0; ss < S_SPLIT; ss += 2) {
            float4 v0 = gp[(size_t)(b * S_SPLIT + ss) * DSTRIDE + tid];
            float4 v1 = gp[(size_t)(b * S_SPLIT + ss + 1) * DSTRIDE + tid];
            ACC4(r0, v0); ACC4(r1, v1);
        }
        ACC4(r0, r1);
        float inv = 1.f / denom;
        r0.x *= inv; r0.y *= inv; r0.z *= inv; r0.w *= inv;
        reinterpret_cast<float4*>(out)[(size_t)b * DSTRIDE + tid] = r0;

        if (tid == 0) g_sem[b] = 0;  // reset for next graph replay
    }
}

extern "C" void kernel_launch(void* const* d_in, const int* in_sizes, int n_in,
                              void* d_out, int out_size) {
    const float* x = (const float*)d_in[0];
    const int* mask = (const int*)d_in[1];
    float* out = (float*)d_out;

    dim3 grid(S_SPLIT, B_DIM);
    mp_fused_kernel<<<grid, TPB>>>(x, mask, out);
}